// round 14
// baseline (speedup 1.0000x reference)
#include <cuda_runtime.h>
#include <cuda_fp16.h>
#include <cstdint>

#define NH 8
#define SEQ 4096
#define HD 128
#define WIN 256
#define BQ 128
#define BK 64
#define NT 6                   // key tiles: span 384 = 128 + 256
#define KSTR 136               // halves per smem tile row (128 + 8 pad)
#define TILE_B (64 * KSTR * 2) // 17408 bytes per 64x128 tile
#define STAGE_B (2 * TILE_B)   // k + v per tile
#define SMEM_TOTAL (NT * STAGE_B)   // 208896 — all 6 tiles resident
#define NTHR 320               // 8 consumer warps + 2 producer warps

__device__ __forceinline__ unsigned smem_u32(const void* p) {
    unsigned a;
    asm("{ .reg .u64 t; cvta.to.shared.u64 t, %1; cvt.u32.u64 %0, t; }" : "=r"(a) : "l"(p));
    return a;
}

#define BAR_SYNC(id)   asm volatile("bar.sync %0, %1;"   :: "r"(id), "r"(NTHR) : "memory")
#define BAR_ARRIVE(id) asm volatile("bar.arrive %0, %1;" :: "r"(id), "r"(NTHR) : "memory")

#define LDSM_X4(r0,r1,r2,r3,a) \
    asm volatile("ldmatrix.sync.aligned.m8n8.x4.shared.b16 {%0,%1,%2,%3}, [%4];" \
        : "=r"(r0),"=r"(r1),"=r"(r2),"=r"(r3) : "r"(a))
#define LDSM_X4T(r0,r1,r2,r3,a) \
    asm volatile("ldmatrix.sync.aligned.m8n8.x4.trans.shared.b16 {%0,%1,%2,%3}, [%4];" \
        : "=r"(r0),"=r"(r1),"=r"(r2),"=r"(r3) : "r"(a))

#define MMA_F16(c,a0,a1,a2,a3,b0,b1) \
    asm volatile("mma.sync.aligned.m16n8k16.row.col.f32.f16.f16.f32 " \
        "{%0,%1,%2,%3},{%4,%5,%6,%7},{%8,%9},{%0,%1,%2,%3};" \
        : "+f"((c)[0]),"+f"((c)[1]),"+f"((c)[2]),"+f"((c)[3]) \
        : "r"(a0),"r"(a1),"r"(a2),"r"(a3),"r"(b0),"r"(b1))

// QK for one 64-key tile with chunk bounds [nplo, nphi] (16-key chunks)
__device__ __forceinline__ void do_qk(unsigned bufK, const unsigned qf[8][4],
                                      float s[8][4], int kb_r, int kb_c,
                                      int nplo, int nphi) {
    #pragma unroll
    for (int j = 0; j < 8; ++j) { s[j][0] = s[j][1] = s[j][2] = s[j][3] = 0.0f; }
    #pragma unroll
    for (int np = 0; np < 4; ++np) {
        if (np < nplo || np > nphi) continue;   // uniform per-warp branch
        #pragma unroll
        for (int kc = 0; kc < 8; ++kc) {
            unsigned off = (unsigned)((np * 16 + kb_r) * KSTR + kc * 16 + kb_c) * 2u;
            unsigned k0, k1, k2, k3;
            LDSM_X4(k0, k1, k2, k3, bufK + off);
            MMA_F16(s[2 * np],     qf[kc][0], qf[kc][1], qf[kc][2], qf[kc][3], k0, k1);
            MMA_F16(s[2 * np + 1], qf[kc][0], qf[kc][1], qf[kc][2], qf[kc][3], k2, k3);
        }
    }
}

// producer: stage rows [p*32, p*32+32) of one (K,V) tile: fp32 gmem -> fp16 smem
__device__ __forceinline__ void produce_half_tile(char* dstK, const float* gk,
                                                  const float* gv, int kb,
                                                  int p, int l) {
    #pragma unroll 8
    for (int i = 0; i < 32; ++i) {
        int idx = l + i * 32;                 // 0..1023
        int r = (idx >> 5) + p * 32;          // 0..63
        int c = idx & 31;                     // float4 col
        size_t go = (size_t)(kb + r) * HD + c * 4;
        float4 kx = *reinterpret_cast<const float4*>(gk + go);
        float4 vx = *reinterpret_cast<const float4*>(gv + go);
        __half2 ka = __floats2half2_rn(kx.x, kx.y), kb2 = __floats2half2_rn(kx.z, kx.w);
        __half2 va = __floats2half2_rn(vx.x, vx.y), vb2 = __floats2half2_rn(vx.z, vx.w);
        uint2 kp, vp;
        kp.x = *reinterpret_cast<unsigned*>(&ka); kp.y = *reinterpret_cast<unsigned*>(&kb2);
        vp.x = *reinterpret_cast<unsigned*>(&va); vp.y = *reinterpret_cast<unsigned*>(&vb2);
        unsigned so = (unsigned)(r * KSTR + c * 4) * 2u;
        *reinterpret_cast<uint2*>(dstK + so)          = kp;
        *reinterpret_cast<uint2*>(dstK + TILE_B + so) = vp;
    }
}

__global__ void __launch_bounds__(NTHR, 1)
attn_kernel(const float* __restrict__ qin, const float* __restrict__ kin,
            const float* __restrict__ vin, float* __restrict__ out) {
    extern __shared__ char smraw[];
    const unsigned sb = smem_u32(smraw);

    const int tid = threadIdx.x;
    const int w   = tid >> 5;
    const int l   = tid & 31;
    const int tq  = blockIdx.x;
    const int h   = blockIdx.y;
    const int q0  = tq * BQ;
    const int kbase = q0 - WIN;
    const int t0 = (q0 >= WIN) ? 0 : (WIN - q0) / BK;

    const float* gk = kin + (size_t)h * SEQ * HD;
    const float* gv = vin + (size_t)h * SEQ * HD;

    // ================= producer warps (w = 8, 9) =================
    if (w >= 8) {
        const int p = w - 8;
        #pragma unroll 1
        for (int t = t0; t < NT; ++t) {
            produce_half_tile(smraw + t * STAGE_B, gk, gv, kbase + t * BK, p, l);
            BAR_ARRIVE(t + 1);    // bar id = tile index + 1 (1..6)
        }
        return;
    }

    // ================= consumer warps (w = 0..7) =================
    const int g   = l >> 2;
    const int q2  = l & 3;

    // ---- load + scale + convert Q fragments (overlaps producer staging) ----
    const float QSCALE = 0.12751744f;   // log2(e)/sqrt(128): softmax = bare ex2
    const int r1 = w * 16 + g, r2 = r1 + 8;
    const float* gq = qin + ((size_t)h * SEQ + q0) * HD;
    unsigned qf[8][4];
    #pragma unroll
    for (int kc = 0; kc < 8; ++kc) {
        int c0 = kc * 16 + q2 * 2;
        float2 x[4];
        x[0] = *reinterpret_cast<const float2*>(gq + (size_t)r1 * HD + c0);
        x[1] = *reinterpret_cast<const float2*>(gq + (size_t)r2 * HD + c0);
        x[2] = *reinterpret_cast<const float2*>(gq + (size_t)r1 * HD + c0 + 8);
        x[3] = *reinterpret_cast<const float2*>(gq + (size_t)r2 * HD + c0 + 8);
        #pragma unroll
        for (int j = 0; j < 4; ++j) {
            __half2 hx = __floats2half2_rn(x[j].x * QSCALE, x[j].y * QSCALE);
            qf[kc][j] = *reinterpret_cast<unsigned*>(&hx);
        }
    }

    // ---- ldmatrix lane address patterns ----
    const int a_r  = (l & 7) + (((l >> 3) & 1) << 3);   // V pattern
    const int a_c  = ((l >> 4) & 1) << 3;
    const int kb_r = (l & 7) + (((l >> 4) & 1) << 3);   // K B pattern
    const int kb_c = ((l >> 3) & 1) << 3;

    float o[16][4];
    #pragma unroll
    for (int d = 0; d < 16; ++d) { o[d][0] = o[d][1] = o[d][2] = o[d][3] = 0.0f; }
    float ss[4] = {0.0f, 0.0f, 0.0f, 0.0f};   // row sums via ones-MMA
    const unsigned ONES = 0x3C003C00u;          // fp16 {1,1}
    const int qi1 = q0 + w * 16 + g;
    const int qi2 = qi1 + 8;

    // ---- per-warp exact tile range ----
    const int wlo = (w >= 4) ? 1 : 0;
    const int tlo = (t0 > wlo) ? t0 : wlo;
    const int thi = (w >= 4) ? (NT - 1) : (NT - 2);

    #define CHUNK_LO(A) (((A) > 14) ? (((A) + 1) >> 4) : 0)
    #define CHUNK_HI(A) min(3, ((A) + 271) >> 4)

    float s[8][4];

    #pragma unroll 1
    for (int t = t0; t < NT; ++t) {
        if (t == t0) {                    // wait for tile t0, prime its scores
            BAR_SYNC(t + 1);
            if (t >= tlo) {               // (t <= thi always at t0)
                int A = 16 * w - 64 * t;
                do_qk(sb + t * STAGE_B, qf, s, kb_r, kb_c, CHUNK_LO(A), CHUNK_HI(A));
            }
        }

        const bool active = (t >= tlo && t <= thi);
        const int kb = kbase + t * BK;
        const int A = 16 * w - 64 * t;
        const int clo = CHUNK_LO(A), chi = CHUNK_HI(A);

        unsigned pa[8][2];
        if (active) {
            const bool needLower = (A >= 0);
            const bool needUpper = (A < -193);
            #pragma unroll
            for (int j = 0; j < 8; ++j) {
                int kj0 = kb + j * 8 + q2 * 2;
                float s0 = s[j][0], s1 = s[j][1], s2 = s[j][2], s3 = s[j][3];
                if (needLower) {
                    if (kj0     < qi1 - (WIN - 1)) s0 = -1e30f;
                    if (kj0 + 1 < qi1 - (WIN - 1)) s1 = -1e30f;
                    if (kj0     < qi2 - (WIN - 1)) s2 = -1e30f;
                    if (kj0 + 1 < qi2 - (WIN - 1)) s3 = -1e30f;
                }
                if (needUpper) {
                    if (kj0     > qi1) s0 = -1e30f;
                    if (kj0 + 1 > qi1) s1 = -1e30f;
                    if (kj0     > qi2) s2 = -1e30f;
                    if (kj0 + 1 > qi2) s3 = -1e30f;
                }
                unsigned u0, u1;
                asm("cvt.rn.f16x2.f32 %0, %1, %2;" : "=r"(u0) : "f"(s1), "f"(s0));
                asm("cvt.rn.f16x2.f32 %0, %1, %2;" : "=r"(u1) : "f"(s3), "f"(s2));
                asm("ex2.approx.f16x2 %0, %1;" : "=r"(pa[j][0]) : "r"(u0));
                asm("ex2.approx.f16x2 %0, %1;" : "=r"(pa[j][1]) : "r"(u1));
            }
        }

        // wait for tile t+1 and prefetch its scores (overlaps PV below)
        if (t + 1 < NT) {
            BAR_SYNC(t + 2);
            if (t + 1 >= tlo && t + 1 <= thi) {
                int A1 = 16 * w - 64 * (t + 1);
                do_qk(sb + (t + 1) * STAGE_B, qf, s, kb_r, kb_c, CHUNK_LO(A1), CHUNK_HI(A1));
            }
        }

        if (active) {
            const unsigned bufV = sb + t * STAGE_B + TILE_B;
            #pragma unroll
            for (int kc = 0; kc < 4; ++kc) {
                if (kc < clo || kc > chi) continue;
                unsigned a0 = pa[2 * kc][0], a1 = pa[2 * kc][1];
                unsigned a2 = pa[2 * kc + 1][0], a3 = pa[2 * kc + 1][1];
                MMA_F16(ss, a0, a1, a2, a3, ONES, ONES);
                #pragma unroll
                for (int dp = 0; dp < 8; ++dp) {
                    unsigned v0, v1, v2, v3;
                    LDSM_X4T(v0, v1, v2, v3,
                             bufV + (unsigned)((kc * 16 + a_r) * KSTR + dp * 16 + a_c) * 2u);
                    MMA_F16(o[2 * dp],     a0, a1, a2, a3, v0, v1);
                    MMA_F16(o[2 * dp + 1], a0, a1, a2, a3, v2, v3);
                }
            }
        }
    }

    // ---- finalize: ss holds full row sums ----
    const float inv1 = 1.0f / ss[0], inv2 = 1.0f / ss[2];

    float* o1 = out + ((size_t)h * SEQ + qi1) * HD;
    float* o2 = out + ((size_t)h * SEQ + qi2) * HD;
    #pragma unroll
    for (int d = 0; d < 16; ++d) {
        float2 x1 = make_float2(o[d][0] * inv1, o[d][1] * inv1);
        float2 x2 = make_float2(o[d][2] * inv2, o[d][3] * inv2);
        *reinterpret_cast<float2*>(o1 + d * 8 + q2 * 2) = x1;
        *reinterpret_cast<float2*>(o2 + d * 8 + q2 * 2) = x2;
    }
}

extern "C" void kernel_launch(void* const* d_in, const int* in_sizes, int n_in,
                              void* d_out, int out_size) {
    const float* q = (const float*)d_in[0];
    const float* k = (const float*)d_in[1];
    const float* v = (const float*)d_in[2];
    float* out = (float*)d_out;

    cudaFuncSetAttribute(attn_kernel, cudaFuncAttributeMaxDynamicSharedMemorySize, SMEM_TOTAL);
    attn_kernel<<<dim3(SEQ / BQ, NH), NTHR, SMEM_TOTAL>>>(q, k, v, out);
}

// round 15
// speedup vs baseline: 1.1062x; 1.1062x over previous
#include <cuda_runtime.h>
#include <cuda_fp16.h>
#include <cstdint>

#define NH 8
#define SEQ 4096
#define HD 128
#define WIN 256
#define BQ 64
#define BK 64
#define NT 5                   // key tiles: span 320 = 64 + 256
#define NRING 3
#define KSTR 136               // halves per smem tile row (128 + 8 pad)
#define TILE_B (64 * KSTR * 2) // 17408 bytes per 64x128 tile
#define STAGE_B (2 * TILE_B)   // k + v per tile
#define SMEM_TOTAL (NRING * STAGE_B)   // 104448 — ring of 3, fits 2 CTAs/SM

__device__ __forceinline__ unsigned smem_u32(const void* p) {
    unsigned a;
    asm("{ .reg .u64 t; cvta.to.shared.u64 t, %1; cvt.u32.u64 %0, t; }" : "=r"(a) : "l"(p));
    return a;
}

#define LDSM_X4(r0,r1,r2,r3,a) \
    asm volatile("ldmatrix.sync.aligned.m8n8.x4.shared.b16 {%0,%1,%2,%3}, [%4];" \
        : "=r"(r0),"=r"(r1),"=r"(r2),"=r"(r3) : "r"(a))
#define LDSM_X4T(r0,r1,r2,r3,a) \
    asm volatile("ldmatrix.sync.aligned.m8n8.x4.trans.shared.b16 {%0,%1,%2,%3}, [%4];" \
        : "=r"(r0),"=r"(r1),"=r"(r2),"=r"(r3) : "r"(a))

#define MMA_F16(c,a0,a1,a2,a3,b0,b1) \
    asm volatile("mma.sync.aligned.m16n8k16.row.col.f32.f16.f16.f32 " \
        "{%0,%1,%2,%3},{%4,%5,%6,%7},{%8,%9},{%0,%1,%2,%3};" \
        : "+f"((c)[0]),"+f"((c)[1]),"+f"((c)[2]),"+f"((c)[3]) \
        : "r"(a0),"r"(a1),"r"(a2),"r"(a3),"r"(b0),"r"(b1))

// QK for one 64-key tile with chunk bounds [nplo, nphi] (16-key chunks)
__device__ __forceinline__ void do_qk(unsigned bufK, const unsigned qf[8][4],
                                      float s[8][4], int kb_r, int kb_c,
                                      int nplo, int nphi) {
    #pragma unroll
    for (int j = 0; j < 8; ++j) { s[j][0] = s[j][1] = s[j][2] = s[j][3] = 0.0f; }
    #pragma unroll
    for (int np = 0; np < 4; ++np) {
        if (np < nplo || np > nphi) continue;   // uniform per-warp branch
        #pragma unroll
        for (int kc = 0; kc < 8; ++kc) {
            unsigned off = (unsigned)((np * 16 + kb_r) * KSTR + kc * 16 + kb_c) * 2u;
            unsigned k0, k1, k2, k3;
            LDSM_X4(k0, k1, k2, k3, bufK + off);
            MMA_F16(s[2 * np],     qf[kc][0], qf[kc][1], qf[kc][2], qf[kc][3], k0, k1);
            MMA_F16(s[2 * np + 1], qf[kc][0], qf[kc][1], qf[kc][2], qf[kc][3], k2, k3);
        }
    }
}

// stage one (K,V) 64x128 tile: fp32 gmem -> fp16 smem; 128 threads, 16 chunks each
__device__ __forceinline__ void stage_tile(char* dstK, const float* gk, const float* gv,
                                           int kb, int tid) {
    #pragma unroll
    for (int i = 0; i < 16; ++i) {
        int idx = tid + i * 128;        // 0..2047: r = row, c = float4 col
        int r = idx >> 5, c = idx & 31;
        size_t go = (size_t)(kb + r) * HD + c * 4;
        float4 kx = *reinterpret_cast<const float4*>(gk + go);
        float4 vx = *reinterpret_cast<const float4*>(gv + go);
        __half2 ka = __floats2half2_rn(kx.x, kx.y), kb2 = __floats2half2_rn(kx.z, kx.w);
        __half2 va = __floats2half2_rn(vx.x, vx.y), vb2 = __floats2half2_rn(vx.z, vx.w);
        uint2 kp, vp;
        kp.x = *reinterpret_cast<unsigned*>(&ka); kp.y = *reinterpret_cast<unsigned*>(&kb2);
        vp.x = *reinterpret_cast<unsigned*>(&va); vp.y = *reinterpret_cast<unsigned*>(&vb2);
        unsigned so = (unsigned)(r * KSTR + c * 4) * 2u;
        *reinterpret_cast<uint2*>(dstK + so)          = kp;
        *reinterpret_cast<uint2*>(dstK + TILE_B + so) = vp;
    }
}

__global__ void __launch_bounds__(128, 2)
attn_kernel(const float* __restrict__ qin, const float* __restrict__ kin,
            const float* __restrict__ vin, float* __restrict__ out) {
    extern __shared__ char smraw[];
    const unsigned sb = smem_u32(smraw);

    const int tid = threadIdx.x;
    const int w   = tid >> 5;          // 0..3
    const int l   = tid & 31;
    const int g   = l >> 2;
    const int q2  = l & 3;
    const int tq  = blockIdx.x;        // 0..63
    const int h   = blockIdx.y;
    const int q0  = tq * BQ;
    const int kbase = q0 - WIN;
    const int t0 = (q0 >= WIN) ? 0 : (WIN - q0) / BK;

    const float* gk = kin + (size_t)h * SEQ * HD;
    const float* gv = vin + (size_t)h * SEQ * HD;

    // ---- load + scale + convert Q fragments from fp32 gmem ----
    const float QSCALE = 0.12751744f;   // log2(e)/sqrt(128): softmax = bare ex2
    const int r1 = w * 16 + g, r2 = r1 + 8;
    const float* gq = qin + ((size_t)h * SEQ + q0) * HD;
    unsigned qf[8][4];
    #pragma unroll
    for (int kc = 0; kc < 8; ++kc) {
        int c0 = kc * 16 + q2 * 2;
        float2 x[4];
        x[0] = *reinterpret_cast<const float2*>(gq + (size_t)r1 * HD + c0);
        x[1] = *reinterpret_cast<const float2*>(gq + (size_t)r2 * HD + c0);
        x[2] = *reinterpret_cast<const float2*>(gq + (size_t)r1 * HD + c0 + 8);
        x[3] = *reinterpret_cast<const float2*>(gq + (size_t)r2 * HD + c0 + 8);
        #pragma unroll
        for (int j = 0; j < 4; ++j) {
            __half2 hx = __floats2half2_rn(x[j].x * QSCALE, x[j].y * QSCALE);
            qf[kc][j] = *reinterpret_cast<unsigned*>(&hx);
        }
    }

    // ---- ldmatrix lane address patterns ----
    const int a_r  = (l & 7) + (((l >> 3) & 1) << 3);   // V pattern
    const int a_c  = ((l >> 4) & 1) << 3;
    const int kb_r = (l & 7) + (((l >> 4) & 1) << 3);   // K B pattern
    const int kb_c = ((l >> 3) & 1) << 3;

    float o[16][4];
    #pragma unroll
    for (int d = 0; d < 16; ++d) { o[d][0] = o[d][1] = o[d][2] = o[d][3] = 0.0f; }
    float ss[4] = {0.0f, 0.0f, 0.0f, 0.0f};   // row sums via ones-MMA
    const unsigned ONES = 0x3C003C00u;          // fp16 {1,1}
    const int qi1 = q0 + w * 16 + g;
    const int qi2 = qi1 + 8;

    #define CHUNK_LO(A) (((A) > 14) ? (((A) + 1) >> 4) : 0)
    #define CHUNK_HI(A) min(3, ((A) + 271) >> 4)

    // ---- prologue: stage tiles t0, t0+1 into ring; publish; prime QK(t0) ----
    stage_tile(smraw + (t0 % NRING) * STAGE_B, gk, gv, kbase + t0 * BK, tid);
    if (t0 + 1 < NT)
        stage_tile(smraw + ((t0 + 1) % NRING) * STAGE_B, gk, gv, kbase + (t0 + 1) * BK, tid);
    __syncthreads();

    float s[8][4];
    {
        int A = 16 * w - 64 * t0;
        do_qk(sb + (t0 % NRING) * STAGE_B, qf, s, kb_r, kb_c, CHUNK_LO(A), CHUNK_HI(A));
    }

    // ---- ring-pipelined loop: stage(t+2) overlapped by sibling CTA's compute ----
    #pragma unroll 1
    for (int t = t0; t < NT; ++t) {
        if (t + 2 < NT)   // write slot (t+2)%3 == (t-1)%3: freed by prev barrier
            stage_tile(smraw + ((t + 2) % NRING) * STAGE_B, gk, gv,
                       kbase + (t + 2) * BK, tid);

        const int kb = kbase + t * BK;
        const int A = 16 * w - 64 * t;
        const int clo = CHUNK_LO(A), chi = CHUNK_HI(A);
        const bool needLower = (A >= 0);
        const bool needUpper = (A < -193);

        unsigned pa[8][2];
        #pragma unroll
        for (int j = 0; j < 8; ++j) {
            int kj0 = kb + j * 8 + q2 * 2;
            float s0 = s[j][0], s1 = s[j][1], s2 = s[j][2], s3 = s[j][3];
            if (needLower) {
                if (kj0     < qi1 - (WIN - 1)) s0 = -1e30f;
                if (kj0 + 1 < qi1 - (WIN - 1)) s1 = -1e30f;
                if (kj0     < qi2 - (WIN - 1)) s2 = -1e30f;
                if (kj0 + 1 < qi2 - (WIN - 1)) s3 = -1e30f;
            }
            if (needUpper) {
                if (kj0     > qi1) s0 = -1e30f;
                if (kj0 + 1 > qi1) s1 = -1e30f;
                if (kj0     > qi2) s2 = -1e30f;
                if (kj0 + 1 > qi2) s3 = -1e30f;
            }
            unsigned u0, u1;
            asm("cvt.rn.f16x2.f32 %0, %1, %2;" : "=r"(u0) : "f"(s1), "f"(s0));
            asm("cvt.rn.f16x2.f32 %0, %1, %2;" : "=r"(u1) : "f"(s3), "f"(s2));
            asm("ex2.approx.f16x2 %0, %1;" : "=r"(pa[j][0]) : "r"(u0));
            asm("ex2.approx.f16x2 %0, %1;" : "=r"(pa[j][1]) : "r"(u1));
        }

        // QK(t+1): slot (t+1)%3 was published by previous barrier (or prologue)
        if (t + 1 < NT) {
            int A1 = 16 * w - 64 * (t + 1);
            do_qk(sb + ((t + 1) % NRING) * STAGE_B, qf, s, kb_r, kb_c,
                  CHUNK_LO(A1), CHUNK_HI(A1));
        }

        // PV(t): O += P @ V; row sums via ones-MMA (masked p exactly 0)
        const unsigned bufV = sb + (t % NRING) * STAGE_B + TILE_B;
        #pragma unroll
        for (int kc = 0; kc < 4; ++kc) {
            if (kc < clo || kc > chi) continue;
            unsigned a0 = pa[2 * kc][0], a1 = pa[2 * kc][1];
            unsigned a2 = pa[2 * kc + 1][0], a3 = pa[2 * kc + 1][1];
            MMA_F16(ss, a0, a1, a2, a3, ONES, ONES);
            #pragma unroll
            for (int dp = 0; dp < 8; ++dp) {
                unsigned v0, v1, v2, v3;
                LDSM_X4T(v0, v1, v2, v3,
                         bufV + (unsigned)((kc * 16 + a_r) * KSTR + dp * 16 + a_c) * 2u);
                MMA_F16(o[2 * dp],     a0, a1, a2, a3, v0, v1);
                MMA_F16(o[2 * dp + 1], a0, a1, a2, a3, v2, v3);
            }
        }

        __syncthreads();   // publish stage(t+2); frees slot t%3 for iter t+1
    }

    // ---- finalize: ss holds full row sums ----
    const float inv1 = 1.0f / ss[0], inv2 = 1.0f / ss[2];

    float* o1 = out + ((size_t)h * SEQ + qi1) * HD;
    float* o2 = out + ((size_t)h * SEQ + qi2) * HD;
    #pragma unroll
    for (int d = 0; d < 16; ++d) {
        float2 x1 = make_float2(o[d][0] * inv1, o[d][1] * inv1);
        float2 x2 = make_float2(o[d][2] * inv2, o[d][3] * inv2);
        *reinterpret_cast<float2*>(o1 + d * 8 + q2 * 2) = x1;
        *reinterpret_cast<float2*>(o2 + d * 8 + q2 * 2) = x2;
    }
}

extern "C" void kernel_launch(void* const* d_in, const int* in_sizes, int n_in,
                              void* d_out, int out_size) {
    const float* q = (const float*)d_in[0];
    const float* k = (const float*)d_in[1];
    const float* v = (const float*)d_in[2];
    float* out = (float*)d_out;

    cudaFuncSetAttribute(attn_kernel, cudaFuncAttributeMaxDynamicSharedMemorySize, SMEM_TOTAL);
    attn_kernel<<<dim3(SEQ / BQ, NH), 128, SMEM_TOTAL>>>(q, k, v, out);
}

// round 16
// speedup vs baseline: 1.2328x; 1.1145x over previous
#include <cuda_runtime.h>
#include <cuda_fp16.h>
#include <cstdint>

#define NH 8
#define SEQ 4096
#define HD 128
#define WIN 256
#define BQ 128
#define BK 64
#define NT 6                   // key tiles: span 384 = 128 + 256
#define KSTR 136               // halves per smem tile row (128 + 8 pad)
#define TILE_B (64 * KSTR * 2) // 17408 bytes per 64x128 tile
#define STAGE_B (2 * TILE_B)   // k + v per tile
#define SMEM_TOTAL (NT * STAGE_B)   // 208896 — all 6 tiles resident

__device__ __forceinline__ unsigned smem_u32(const void* p) {
    unsigned a;
    asm("{ .reg .u64 t; cvta.to.shared.u64 t, %1; cvt.u32.u64 %0, t; }" : "=r"(a) : "l"(p));
    return a;
}

#define LDSM_X4(r0,r1,r2,r3,a) \
    asm volatile("ldmatrix.sync.aligned.m8n8.x4.shared.b16 {%0,%1,%2,%3}, [%4];" \
        : "=r"(r0),"=r"(r1),"=r"(r2),"=r"(r3) : "r"(a))
#define LDSM_X4T(r0,r1,r2,r3,a) \
    asm volatile("ldmatrix.sync.aligned.m8n8.x4.trans.shared.b16 {%0,%1,%2,%3}, [%4];" \
        : "=r"(r0),"=r"(r1),"=r"(r2),"=r"(r3) : "r"(a))

#define MMA_F16(c,a0,a1,a2,a3,b0,b1) \
    asm volatile("mma.sync.aligned.m16n8k16.row.col.f32.f16.f16.f32 " \
        "{%0,%1,%2,%3},{%4,%5,%6,%7},{%8,%9},{%0,%1,%2,%3};" \
        : "+f"((c)[0]),"+f"((c)[1]),"+f"((c)[2]),"+f"((c)[3]) \
        : "r"(a0),"r"(a1),"r"(a2),"r"(a3),"r"(b0),"r"(b1))

// QK for one 64-key tile with chunk bounds [nplo, nphi] (16-key chunks)
__device__ __forceinline__ void do_qk(unsigned bufK, const unsigned qf[8][4],
                                      float s[8][4], int kb_r, int kb_c,
                                      int nplo, int nphi) {
    #pragma unroll
    for (int np = 0; np < 4; ++np) {
        if (np < nplo || np > nphi) continue;   // uniform per-warp branch
        s[2*np][0] = s[2*np][1] = s[2*np][2] = s[2*np][3] = 0.0f;
        s[2*np+1][0] = s[2*np+1][1] = s[2*np+1][2] = s[2*np+1][3] = 0.0f;
        #pragma unroll
        for (int kc = 0; kc < 8; ++kc) {
            unsigned off = (unsigned)((np * 16 + kb_r) * KSTR + kc * 16 + kb_c) * 2u;
            unsigned k0, k1, k2, k3;
            LDSM_X4(k0, k1, k2, k3, bufK + off);
            MMA_F16(s[2 * np],     qf[kc][0], qf[kc][1], qf[kc][2], qf[kc][3], k0, k1);
            MMA_F16(s[2 * np + 1], qf[kc][0], qf[kc][1], qf[kc][2], qf[kc][3], k2, k3);
        }
    }
}

__global__ void __launch_bounds__(256, 1)
attn_kernel(const float* __restrict__ qin, const float* __restrict__ kin,
            const float* __restrict__ vin, float* __restrict__ out) {
    extern __shared__ char smraw[];
    const unsigned sb = smem_u32(smraw);

    const int tid = threadIdx.x;
    const int w   = tid >> 5;
    const int l   = tid & 31;
    const int g   = l >> 2;
    const int q2  = l & 3;
    const int tq  = blockIdx.x;
    const int h   = blockIdx.y;
    const int q0  = tq * BQ;
    const int kbase = q0 - WIN;
    const int t0 = (q0 >= WIN) ? 0 : (WIN - q0) / BK;

    const float* gk = kin + (size_t)h * SEQ * HD;
    const float* gv = vin + (size_t)h * SEQ * HD;

    // ---- load + scale + convert Q fragments from fp32 gmem (issue LDGs early) ----
    const float QSCALE = 0.12751744f;   // log2(e)/sqrt(128): softmax = bare ex2
    const int r1 = w * 16 + g, r2 = r1 + 8;
    const float* gq = qin + ((size_t)h * SEQ + q0) * HD;
    unsigned qf[8][4];
    #pragma unroll
    for (int kc = 0; kc < 8; ++kc) {
        int c0 = kc * 16 + q2 * 2;
        float2 x[4];
        x[0] = *reinterpret_cast<const float2*>(gq + (size_t)r1 * HD + c0);
        x[1] = *reinterpret_cast<const float2*>(gq + (size_t)r2 * HD + c0);
        x[2] = *reinterpret_cast<const float2*>(gq + (size_t)r1 * HD + c0 + 8);
        x[3] = *reinterpret_cast<const float2*>(gq + (size_t)r2 * HD + c0 + 8);
        #pragma unroll
        for (int j = 0; j < 4; ++j) {
            __half2 hx = __floats2half2_rn(x[j].x * QSCALE, x[j].y * QSCALE);
            qf[kc][j] = *reinterpret_cast<unsigned*>(&hx);
        }
    }

    // ---- fused staging: fp32 K/V -> fp16 smem, fully unrolled for MLP ----
    #pragma unroll
    for (int tt = 0; tt < NT; ++tt) {
        if (tt < t0) continue;              // uniform per-CTA guard
        const int kb = kbase + tt * BK;     // >= 0 for tt >= t0
        char* dstK = smraw + tt * STAGE_B;
        #pragma unroll
        for (int i = 0; i < 8; ++i) {
            int idx = tid + i * 256;        // 0..2047: r = row, c = float4 col
            int r = idx >> 5, c = idx & 31;
            size_t go = (size_t)(kb + r) * HD + c * 4;
            float4 kx = *reinterpret_cast<const float4*>(gk + go);
            float4 vx = *reinterpret_cast<const float4*>(gv + go);
            __half2 ka = __floats2half2_rn(kx.x, kx.y), kb2 = __floats2half2_rn(kx.z, kx.w);
            __half2 va = __floats2half2_rn(vx.x, vx.y), vb2 = __floats2half2_rn(vx.z, vx.w);
            uint2 kp, vp;
            kp.x = *reinterpret_cast<unsigned*>(&ka); kp.y = *reinterpret_cast<unsigned*>(&kb2);
            vp.x = *reinterpret_cast<unsigned*>(&va); vp.y = *reinterpret_cast<unsigned*>(&vb2);
            unsigned so = (unsigned)(r * KSTR + c * 4) * 2u;
            *reinterpret_cast<uint2*>(dstK + so)          = kp;
            *reinterpret_cast<uint2*>(dstK + TILE_B + so) = vp;
        }
    }

    // ---- ldmatrix lane address patterns ----
    const int a_r  = (l & 7) + (((l >> 3) & 1) << 3);   // V pattern
    const int a_c  = ((l >> 4) & 1) << 3;
    const int kb_r = (l & 7) + (((l >> 4) & 1) << 3);   // K B pattern
    const int kb_c = ((l >> 3) & 1) << 3;

    float o[16][4];
    #pragma unroll
    for (int d = 0; d < 16; ++d) { o[d][0] = o[d][1] = o[d][2] = o[d][3] = 0.0f; }
    float ss[4] = {0.0f, 0.0f, 0.0f, 0.0f};   // row-sum accumulator (via ones-MMA)
    const unsigned ONES = 0x3C003C00u;          // fp16 {1,1}
    const int qi1 = q0 + w * 16 + g;
    const int qi2 = qi1 + 8;

    // ---- per-warp exact tile range ----
    const int wlo = (w >= 4) ? 1 : 0;
    const int tlo = (t0 > wlo) ? t0 : wlo;
    const int thi = (w >= 4) ? (NT - 1) : (NT - 2);

    // chunk bounds for tile t: A = 16w - 64t
    #define CHUNK_LO(A) (((A) > 14) ? (((A) + 1) >> 4) : 0)
    #define CHUNK_HI(A) min(3, ((A) + 271) >> 4)

    // ---- ONE barrier; main loop is sync-free ----
    __syncthreads();

    float s[8][4];
    {
        int A = 16 * w - 64 * tlo;
        do_qk(sb + tlo * STAGE_B, qf, s, kb_r, kb_c, CHUNK_LO(A), CHUNK_HI(A));
    }

    #pragma unroll 1
    for (int t = tlo; t <= thi; ++t) {
        const int kb = kbase + t * BK;
        const int A = 16 * w - 64 * t;
        const int clo = CHUNK_LO(A), chi = CHUNK_HI(A);

        const bool needLower = (A >= 0);          // 64t <= 16w
        const bool needUpper = (A < -193);        // 64t > 16w + 193

        unsigned pa[8][2];
        #pragma unroll
        for (int j = 0; j < 8; ++j) {
            if ((j >> 1) < clo || (j >> 1) > chi) continue;   // dead chunk: no ex2/mask
            int kj0 = kb + j * 8 + q2 * 2;
            float s0 = s[j][0], s1 = s[j][1], s2 = s[j][2], s3 = s[j][3];
            if (needLower) {
                if (kj0     < qi1 - (WIN - 1)) s0 = -1e30f;
                if (kj0 + 1 < qi1 - (WIN - 1)) s1 = -1e30f;
                if (kj0     < qi2 - (WIN - 1)) s2 = -1e30f;
                if (kj0 + 1 < qi2 - (WIN - 1)) s3 = -1e30f;
            }
            if (needUpper) {
                if (kj0     > qi1) s0 = -1e30f;
                if (kj0 + 1 > qi1) s1 = -1e30f;
                if (kj0     > qi2) s2 = -1e30f;
                if (kj0 + 1 > qi2) s3 = -1e30f;
            }
            unsigned u0, u1;
            asm("cvt.rn.f16x2.f32 %0, %1, %2;" : "=r"(u0) : "f"(s1), "f"(s0));
            asm("cvt.rn.f16x2.f32 %0, %1, %2;" : "=r"(u1) : "f"(s3), "f"(s2));
            asm("ex2.approx.f16x2 %0, %1;" : "=r"(pa[j][0]) : "r"(u0));   // masked -> 2^-inf = 0
            asm("ex2.approx.f16x2 %0, %1;" : "=r"(pa[j][1]) : "r"(u1));
        }

        // QK(t+1) overlaps PV(t)
        if (t < thi) {
            int A1 = 16 * w - 64 * (t + 1);
            do_qk(sb + (t + 1) * STAGE_B, qf, s, kb_r, kb_c, CHUNK_LO(A1), CHUNK_HI(A1));
        }

        // PV(t): O += P @ V; row sums via ones-MMA (masked p are exactly 0)
        const unsigned bufV = sb + t * STAGE_B + TILE_B;
        #pragma unroll
        for (int kc = 0; kc < 4; ++kc) {
            if (kc < clo || kc > chi) continue;
            unsigned a0 = pa[2 * kc][0], a1 = pa[2 * kc][1];
            unsigned a2 = pa[2 * kc + 1][0], a3 = pa[2 * kc + 1][1];
            MMA_F16(ss, a0, a1, a2, a3, ONES, ONES);
            #pragma unroll
            for (int dp = 0; dp < 8; ++dp) {
                unsigned v0, v1, v2, v3;
                LDSM_X4T(v0, v1, v2, v3,
                         bufV + (unsigned)((kc * 16 + a_r) * KSTR + dp * 16 + a_c) * 2u);
                MMA_F16(o[2 * dp],     a0, a1, a2, a3, v0, v1);
                MMA_F16(o[2 * dp + 1], a0, a1, a2, a3, v2, v3);
            }
        }
    }

    // ---- finalize: ss already holds full row sums (no shuffles needed) ----
    const float inv1 = 1.0f / ss[0], inv2 = 1.0f / ss[2];

    float* o1 = out + ((size_t)h * SEQ + qi1) * HD;
    float* o2 = out + ((size_t)h * SEQ + qi2) * HD;
    #pragma unroll
    for (int d = 0; d < 16; ++d) {
        float2 x1 = make_float2(o[d][0] * inv1, o[d][1] * inv1);
        float2 x2 = make_float2(o[d][2] * inv2, o[d][3] * inv2);
        *reinterpret_cast<float2*>(o1 + d * 8 + q2 * 2) = x1;
        *reinterpret_cast<float2*>(o2 + d * 8 + q2 * 2) = x2;
    }
}

extern "C" void kernel_launch(void* const* d_in, const int* in_sizes, int n_in,
                              void* d_out, int out_size) {
    const float* q = (const float*)d_in[0];
    const float* k = (const float*)d_in[1];
    const float* v = (const float*)d_in[2];
    float* out = (float*)d_out;

    cudaFuncSetAttribute(attn_kernel, cudaFuncAttributeMaxDynamicSharedMemorySize, SMEM_TOTAL);
    attn_kernel<<<dim3(SEQ / BQ, NH), 256, SMEM_TOTAL>>>(q, k, v, out);
}

// round 17
// speedup vs baseline: 1.3157x; 1.0672x over previous
#include <cuda_runtime.h>
#include <cuda_fp16.h>
#include <cstdint>

#define NH 8
#define SEQ 4096
#define HD 128
#define WIN 256
#define BQ 128
#define BK 64
#define NT 6                   // key tiles: span 384 = 128 + 256
#define KSTR 136               // halves per smem tile row (128 + 8 pad)
#define TILE_B (64 * KSTR * 2) // 17408 bytes per 64x128 tile
#define STAGE_B (2 * TILE_B)   // k + v per tile
#define SMEM_TOTAL (NT * STAGE_B)   // 208896 — all 6 tiles resident

__device__ __forceinline__ unsigned smem_u32(const void* p) {
    unsigned a;
    asm("{ .reg .u64 t; cvta.to.shared.u64 t, %1; cvt.u32.u64 %0, t; }" : "=r"(a) : "l"(p));
    return a;
}

#define LDSM_X4(r0,r1,r2,r3,a) \
    asm volatile("ldmatrix.sync.aligned.m8n8.x4.shared.b16 {%0,%1,%2,%3}, [%4];" \
        : "=r"(r0),"=r"(r1),"=r"(r2),"=r"(r3) : "r"(a))
#define LDSM_X4T(r0,r1,r2,r3,a) \
    asm volatile("ldmatrix.sync.aligned.m8n8.x4.trans.shared.b16 {%0,%1,%2,%3}, [%4];" \
        : "=r"(r0),"=r"(r1),"=r"(r2),"=r"(r3) : "r"(a))

#define MMA_F16(c,a0,a1,a2,a3,b0,b1) \
    asm volatile("mma.sync.aligned.m16n8k16.row.col.f32.f16.f16.f32 " \
        "{%0,%1,%2,%3},{%4,%5,%6,%7},{%8,%9},{%0,%1,%2,%3};" \
        : "+f"((c)[0]),"+f"((c)[1]),"+f"((c)[2]),"+f"((c)[3]) \
        : "r"(a0),"r"(a1),"r"(a2),"r"(a3),"r"(b0),"r"(b1))

// QK for one 64-key tile with chunk bounds [nplo, nphi] (16-key chunks)
__device__ __forceinline__ void do_qk(unsigned bufK, const unsigned qf[8][4],
                                      float s[8][4], int kb_r, int kb_c,
                                      int nplo, int nphi) {
    #pragma unroll
    for (int j = 0; j < 8; ++j) { s[j][0] = s[j][1] = s[j][2] = s[j][3] = 0.0f; }
    #pragma unroll
    for (int np = 0; np < 4; ++np) {
        if (np < nplo || np > nphi) continue;   // uniform per-warp branch
        #pragma unroll
        for (int kc = 0; kc < 8; ++kc) {
            unsigned off = (unsigned)((np * 16 + kb_r) * KSTR + kc * 16 + kb_c) * 2u;
            unsigned k0, k1, k2, k3;
            LDSM_X4(k0, k1, k2, k3, bufK + off);
            MMA_F16(s[2 * np],     qf[kc][0], qf[kc][1], qf[kc][2], qf[kc][3], k0, k1);
            MMA_F16(s[2 * np + 1], qf[kc][0], qf[kc][1], qf[kc][2], qf[kc][3], k2, k3);
        }
    }
}

__global__ void __launch_bounds__(256, 1)
attn_kernel(const float* __restrict__ qin, const float* __restrict__ kin,
            const float* __restrict__ vin, float* __restrict__ out) {
    extern __shared__ char smraw[];
    const unsigned sb = smem_u32(smraw);

    const int tid = threadIdx.x;
    const int w   = tid >> 5;
    const int l   = tid & 31;
    const int g   = l >> 2;
    const int q2  = l & 3;
    const int tq  = blockIdx.x;
    const int h   = blockIdx.y;
    const int q0  = tq * BQ;
    const int kbase = q0 - WIN;
    const int t0 = (q0 >= WIN) ? 0 : (WIN - q0) / BK;

    const float* gk = kin + (size_t)h * SEQ * HD;
    const float* gv = vin + (size_t)h * SEQ * HD;

    // ---- load + scale + convert Q fragments from fp32 gmem (issue LDGs early) ----
    const float QSCALE = 0.12751744f;   // log2(e)/sqrt(128): softmax = bare ex2
    const int r1 = w * 16 + g, r2 = r1 + 8;
    const float* gq = qin + ((size_t)h * SEQ + q0) * HD;
    unsigned qf[8][4];
    #pragma unroll
    for (int kc = 0; kc < 8; ++kc) {
        int c0 = kc * 16 + q2 * 2;
        float2 x[4];
        x[0] = *reinterpret_cast<const float2*>(gq + (size_t)r1 * HD + c0);
        x[1] = *reinterpret_cast<const float2*>(gq + (size_t)r2 * HD + c0);
        x[2] = *reinterpret_cast<const float2*>(gq + (size_t)r1 * HD + c0 + 8);
        x[3] = *reinterpret_cast<const float2*>(gq + (size_t)r2 * HD + c0 + 8);
        #pragma unroll
        for (int j = 0; j < 4; ++j) {
            __half2 hx = __floats2half2_rn(x[j].x * QSCALE, x[j].y * QSCALE);
            qf[kc][j] = *reinterpret_cast<unsigned*>(&hx);
        }
    }

    // ---- fused staging: fp32 K/V -> fp16 smem, fully unrolled for MLP ----
    #pragma unroll
    for (int tt = 0; tt < NT; ++tt) {
        if (tt < t0) continue;              // uniform per-CTA guard
        const int kb = kbase + tt * BK;     // >= 0 for tt >= t0
        char* dstK = smraw + tt * STAGE_B;
        #pragma unroll
        for (int i = 0; i < 8; ++i) {
            int idx = tid + i * 256;        // 0..2047: r = row, c = float4 col
            int r = idx >> 5, c = idx & 31;
            size_t go = (size_t)(kb + r) * HD + c * 4;
            float4 kx = *reinterpret_cast<const float4*>(gk + go);
            float4 vx = *reinterpret_cast<const float4*>(gv + go);
            __half2 ka = __floats2half2_rn(kx.x, kx.y), kb2 = __floats2half2_rn(kx.z, kx.w);
            __half2 va = __floats2half2_rn(vx.x, vx.y), vb2 = __floats2half2_rn(vx.z, vx.w);
            uint2 kp, vp;
            kp.x = *reinterpret_cast<unsigned*>(&ka); kp.y = *reinterpret_cast<unsigned*>(&kb2);
            vp.x = *reinterpret_cast<unsigned*>(&va); vp.y = *reinterpret_cast<unsigned*>(&vb2);
            unsigned so = (unsigned)(r * KSTR + c * 4) * 2u;
            *reinterpret_cast<uint2*>(dstK + so)          = kp;
            *reinterpret_cast<uint2*>(dstK + TILE_B + so) = vp;
        }
    }

    // ---- ldmatrix lane address patterns ----
    const int a_r  = (l & 7) + (((l >> 3) & 1) << 3);   // V pattern
    const int a_c  = ((l >> 4) & 1) << 3;
    const int kb_r = (l & 7) + (((l >> 4) & 1) << 3);   // K B pattern
    const int kb_c = ((l >> 3) & 1) << 3;

    float o[16][4];
    #pragma unroll
    for (int d = 0; d < 16; ++d) { o[d][0] = o[d][1] = o[d][2] = o[d][3] = 0.0f; }
    float ss[4] = {0.0f, 0.0f, 0.0f, 0.0f};   // row-sum accumulator (via ones-MMA)
    const unsigned ONES = 0x3C003C00u;          // fp16 {1,1}
    const int qi1 = q0 + w * 16 + g;
    const int qi2 = qi1 + 8;

    // ---- per-warp exact tile range ----
    const int wlo = (w >= 4) ? 1 : 0;
    const int tlo = (t0 > wlo) ? t0 : wlo;
    const int thi = (w >= 4) ? (NT - 1) : (NT - 2);

    // chunk bounds for tile t: A = 16w - 64t
    #define CHUNK_LO(A) (((A) > 14) ? (((A) + 1) >> 4) : 0)
    #define CHUNK_HI(A) min(3, ((A) + 271) >> 4)

    // ---- ONE barrier; main loop is sync-free ----
    __syncthreads();

    float s[8][4];
    {
        int A = 16 * w - 64 * tlo;
        do_qk(sb + tlo * STAGE_B, qf, s, kb_r, kb_c, CHUNK_LO(A), CHUNK_HI(A));
    }

    #pragma unroll 1
    for (int t = tlo; t <= thi; ++t) {
        const int kb = kbase + t * BK;
        const int A = 16 * w - 64 * t;
        const int clo = CHUNK_LO(A), chi = CHUNK_HI(A);

        const bool needLower = (A >= 0);          // 64t <= 16w
        const bool needUpper = (A < -193);        // 64t > 16w + 193

        unsigned pa[8][2];
        #pragma unroll
        for (int j = 0; j < 8; ++j) {
            int kj0 = kb + j * 8 + q2 * 2;
            float s0 = s[j][0], s1 = s[j][1], s2 = s[j][2], s3 = s[j][3];
            if (needLower) {
                if (kj0     < qi1 - (WIN - 1)) s0 = -1e30f;
                if (kj0 + 1 < qi1 - (WIN - 1)) s1 = -1e30f;
                if (kj0     < qi2 - (WIN - 1)) s2 = -1e30f;
                if (kj0 + 1 < qi2 - (WIN - 1)) s3 = -1e30f;
            }
            if (needUpper) {
                if (kj0     > qi1) s0 = -1e30f;
                if (kj0 + 1 > qi1) s1 = -1e30f;
                if (kj0     > qi2) s2 = -1e30f;
                if (kj0 + 1 > qi2) s3 = -1e30f;
            }
            unsigned u0, u1;
            asm("cvt.rn.f16x2.f32 %0, %1, %2;" : "=r"(u0) : "f"(s1), "f"(s0));
            asm("cvt.rn.f16x2.f32 %0, %1, %2;" : "=r"(u1) : "f"(s3), "f"(s2));
            asm("ex2.approx.f16x2 %0, %1;" : "=r"(pa[j][0]) : "r"(u0));   // masked -> 2^-inf = 0
            asm("ex2.approx.f16x2 %0, %1;" : "=r"(pa[j][1]) : "r"(u1));
        }

        // QK(t+1) overlaps PV(t)
        if (t < thi) {
            int A1 = 16 * w - 64 * (t + 1);
            do_qk(sb + (t + 1) * STAGE_B, qf, s, kb_r, kb_c, CHUNK_LO(A1), CHUNK_HI(A1));
        }

        // PV(t): O += P @ V; row sums via ones-MMA (masked p are exactly 0)
        const unsigned bufV = sb + t * STAGE_B + TILE_B;
        #pragma unroll
        for (int kc = 0; kc < 4; ++kc) {
            if (kc < clo || kc > chi) continue;
            unsigned a0 = pa[2 * kc][0], a1 = pa[2 * kc][1];
            unsigned a2 = pa[2 * kc + 1][0], a3 = pa[2 * kc + 1][1];
            MMA_F16(ss, a0, a1, a2, a3, ONES, ONES);
            #pragma unroll
            for (int dp = 0; dp < 8; ++dp) {
                unsigned v0, v1, v2, v3;
                LDSM_X4T(v0, v1, v2, v3,
                         bufV + (unsigned)((kc * 16 + a_r) * KSTR + dp * 16 + a_c) * 2u);
                MMA_F16(o[2 * dp],     a0, a1, a2, a3, v0, v1);
                MMA_F16(o[2 * dp + 1], a0, a1, a2, a3, v2, v3);
            }
        }
    }

    // ---- finalize: ss already holds full row sums (no shuffles needed) ----
    const float inv1 = 1.0f / ss[0], inv2 = 1.0f / ss[2];

    float* o1 = out + ((size_t)h * SEQ + qi1) * HD;
    float* o2 = out + ((size_t)h * SEQ + qi2) * HD;
    #pragma unroll
    for (int d = 0; d < 16; ++d) {
        float2 x1 = make_float2(o[d][0] * inv1, o[d][1] * inv1);
        float2 x2 = make_float2(o[d][2] * inv2, o[d][3] * inv2);
        *reinterpret_cast<float2*>(o1 + d * 8 + q2 * 2) = x1;
        *reinterpret_cast<float2*>(o2 + d * 8 + q2 * 2) = x2;
    }
}

extern "C" void kernel_launch(void* const* d_in, const int* in_sizes, int n_in,
                              void* d_out, int out_size) {
    const float* q = (const float*)d_in[0];
    const float* k = (const float*)d_in[1];
    const float* v = (const float*)d_in[2];
    float* out = (float*)d_out;

    cudaFuncSetAttribute(attn_kernel, cudaFuncAttributeMaxDynamicSharedMemorySize, SMEM_TOTAL);
    attn_kernel<<<dim3(SEQ / BQ, NH), 256, SMEM_TOTAL>>>(q, k, v, out);
}